// round 5
// baseline (speedup 1.0000x reference)
#include <cuda_runtime.h>
#include <cuda_fp16.h>
#include <cstdint>

#define N_NODES 65536
#define N_EDGES 1048576
#define FEAT    64
#define NB      512
#define NT      256

// ------------------------- device scratch (no allocs) -----------------------
__device__ __align__(16) __half g_support_h[(size_t)N_NODES * FEAT]; // 8 MB
__device__ __align__(16) int   g_cnt[N_NODES];     // zero-init; self-cleaned each run
__device__ __align__(16) int   g_rs[N_NODES + 4];
__device__ __align__(16) int   g_cur[N_NODES];
__device__ __align__(16) int   g_bsum[64];
__device__ __align__(16) int2  g_epair[N_EDGES];
__device__ unsigned g_barcnt;   // 0 after every barrier
__device__ unsigned g_bargen;   // monotonically increasing generation

// ---- packed f32x2 helpers ---------------------------------------------------
__device__ __forceinline__ unsigned long long pk2(float x, float y) {
    unsigned long long r;
    asm("mov.b64 %0, {%1, %2};" : "=l"(r) : "f"(x), "f"(y));
    return r;
}
__device__ __forceinline__ void fma2(unsigned long long& d,
                                     unsigned long long a, unsigned long long b) {
    asm("fma.rn.f32x2 %0, %1, %2, %0;" : "+l"(d) : "l"(a), "l"(b));
}
__device__ __forceinline__ float2 up2(unsigned long long v) {
    float2 f;
    asm("mov.b64 {%0, %1}, %2;" : "=f"(f.x), "=f"(f.y) : "l"(v));
    return f;
}

// ---- device-wide barrier (all NB blocks co-resident by construction) --------
__device__ __forceinline__ void gbar() {
    __syncthreads();
    if (threadIdx.x == 0) {
        __threadfence();
        const unsigned gen = *(volatile unsigned*)&g_bargen;
        if (atomicAdd(&g_barcnt, 1u) == NB - 1u) {
            g_barcnt = 0;
            __threadfence();
            *(volatile unsigned*)&g_bargen = gen + 1u;
        } else {
            while (*(volatile unsigned*)&g_bargen == gen) { __nanosleep(32); }
        }
    }
    __syncthreads();
}

// ---------------------------------------------------------------------------
__global__ __launch_bounds__(NT, 4) void gcn_mono(
    const float* __restrict__ X,    const int*   __restrict__ erow,
    const int*   __restrict__ ecol, const float* __restrict__ eval,
    const float* __restrict__ W,    const float* __restrict__ bias,
    float* __restrict__ out)
{
    __shared__ float4 Ws[64][16];
    __shared__ float4 Xs[64][16];
    __shared__ int    wsum[8];

    const int tid = threadIdx.x;
    const int bid = blockIdx.x;

    // ======================= P1: GEMM (2 tiles/block) + histogram ===========
    {
        const float4* W4 = (const float4*)W;
        const int rt = tid >> 4;
        const int ct = tid & 15;
#pragma unroll
        for (int t = 0; t < 2; t++) {
            const int base = (bid * 2 + t) * 64;
            const float4* X4 = (const float4*)(X + (size_t)base * FEAT);
            float4* XsF = (float4*)Xs;
            float4* WsF = (float4*)Ws;
#pragma unroll
            for (int i = 0; i < 4; i++) {
                const int idx = tid + i * 256;
                XsF[idx] = X4[idx];
                if (t == 0) WsF[idx] = W4[idx];
            }
            __syncthreads();

            unsigned long long acc[4][2];
#pragma unroll
            for (int i = 0; i < 4; i++) {
                acc[i][0] = pk2(0.f, 0.f);
                acc[i][1] = pk2(0.f, 0.f);
            }
#pragma unroll
            for (int kk = 0; kk < 16; kk++) {
                const float4 w0 = Ws[kk * 4 + 0][ct];
                const float4 w1 = Ws[kk * 4 + 1][ct];
                const float4 w2 = Ws[kk * 4 + 2][ct];
                const float4 w3 = Ws[kk * 4 + 3][ct];
                const unsigned long long wp00 = pk2(w0.x, w0.y), wp01 = pk2(w0.z, w0.w);
                const unsigned long long wp10 = pk2(w1.x, w1.y), wp11 = pk2(w1.z, w1.w);
                const unsigned long long wp20 = pk2(w2.x, w2.y), wp21 = pk2(w2.z, w2.w);
                const unsigned long long wp30 = pk2(w3.x, w3.y), wp31 = pk2(w3.z, w3.w);
#pragma unroll
                for (int i = 0; i < 4; i++) {
                    const float4 x = Xs[rt + 16 * i][kk];
                    unsigned long long xx;
                    xx = pk2(x.x, x.x); fma2(acc[i][0], xx, wp00); fma2(acc[i][1], xx, wp01);
                    xx = pk2(x.y, x.y); fma2(acc[i][0], xx, wp10); fma2(acc[i][1], xx, wp11);
                    xx = pk2(x.z, x.z); fma2(acc[i][0], xx, wp20); fma2(acc[i][1], xx, wp21);
                    xx = pk2(x.w, x.w); fma2(acc[i][0], xx, wp30); fma2(acc[i][1], xx, wp31);
                }
            }
#pragma unroll
            for (int i = 0; i < 4; i++) {
                const int row = base + rt + 16 * i;
                const float2 a = up2(acc[i][0]);
                const float2 b = up2(acc[i][1]);
                const __half2 ha = __floats2half2_rn(a.x, a.y);
                const __half2 hb = __floats2half2_rn(b.x, b.y);
                uint2 st;
                st.x = *(const unsigned*)&ha;
                st.y = *(const unsigned*)&hb;
                *(uint2*)(g_support_h + (size_t)row * FEAT + ct * 4) = st;
            }
            __syncthreads();   // smem reused next tile
        }

        // histogram of destination rows: 2 x int4 per thread
        const int4* er4 = (const int4*)erow;
#pragma unroll
        for (int p = 0; p < 2; p++) {
            const int4 r = er4[bid * 512 + p * 256 + tid];
            atomicAdd(&g_cnt[r.x], 1);
            atomicAdd(&g_cnt[r.y], 1);
            atomicAdd(&g_cnt[r.z], 1);
            atomicAdd(&g_cnt[r.w], 1);
        }
    }
    gbar();

    // ======================= P2: per-block scan (blocks 0..63) ==============
    if (bid < 64) {
        const int i = bid * 256 + tid;
        const int4* c4 = (const int4*)g_cnt;
        int4 c;
        c.x = __ldcg(&((const int*)&c4[i])[0]);
        c.y = __ldcg(&((const int*)&c4[i])[1]);
        c.z = __ldcg(&((const int*)&c4[i])[2]);
        c.w = __ldcg(&((const int*)&c4[i])[3]);
        const int s = c.x + c.y + c.z + c.w;

        // block inclusive scan of s
        const int lane = tid & 31, wid = tid >> 5;
        int x = s;
#pragma unroll
        for (int d = 1; d < 32; d <<= 1) {
            const int y = __shfl_up_sync(0xFFFFFFFFu, x, d);
            if (lane >= d) x += y;
        }
        if (lane == 31) wsum[wid] = x;
        __syncthreads();
        if (wid == 0) {
            int w = (lane < 8) ? wsum[lane] : 0;
#pragma unroll
            for (int d = 1; d < 8; d <<= 1) {
                const int y = __shfl_up_sync(0xFFFFFFFFu, w, d);
                if (lane >= d) w += y;
            }
            if (lane < 8) wsum[lane] = w;
        }
        __syncthreads();
        const int incl = x + (wid > 0 ? wsum[wid - 1] : 0);
        const int ex = incl - s;
        ((int4*)g_rs)[i] = make_int4(ex, ex + c.x, ex + c.x + c.y, ex + c.x + c.y + c.z);
        if (tid == 255) g_bsum[bid] = incl;
    }
    gbar();

    // ======================= P3: scan 64 block sums (1 warp) ================
    if (bid == 0 && tid < 32) {
        const int lane = tid;
        const int a = __ldcg(&g_bsum[lane]);
        const int b = __ldcg(&g_bsum[lane + 32]);
        int ia = a, ib = b;
#pragma unroll
        for (int d = 1; d < 32; d <<= 1) {
            const int ya = __shfl_up_sync(0xFFFFFFFFu, ia, d);
            const int yb = __shfl_up_sync(0xFFFFFFFFu, ib, d);
            if (lane >= d) { ia += ya; ib += yb; }
        }
        const int lowtot = __shfl_sync(0xFFFFFFFFu, ia, 31);
        g_bsum[lane]      = ia - a;            // exclusive offsets
        g_bsum[lane + 32] = lowtot + ib - b;
    }
    gbar();

    // ======================= P4: apply offsets, init cursors, clean cnt =====
    if (bid < 64) {
        const int off = __ldcg(&g_bsum[bid]);
        const int i = bid * 256 + tid;
        int4 rs;
        rs.x = __ldcg(&((const int*)&((int4*)g_rs)[i])[0]) + off;
        rs.y = __ldcg(&((const int*)&((int4*)g_rs)[i])[1]) + off;
        rs.z = __ldcg(&((const int*)&((int4*)g_rs)[i])[2]) + off;
        rs.w = __ldcg(&((const int*)&((int4*)g_rs)[i])[3]) + off;
        ((int4*)g_rs)[i]  = rs;
        ((int4*)g_cur)[i] = rs;
        ((int4*)g_cnt)[i] = make_int4(0, 0, 0, 0);   // self-clean for next run
        if (i == 0) g_rs[N_NODES] = N_EDGES;
    }
    gbar();

    // ======================= P5: reorder into CSR pairs =====================
    {
        const int4*   er4 = (const int4*)erow;
        const int4*   ec4 = (const int4*)ecol;
        const float4* ev4 = (const float4*)eval;
#pragma unroll
        for (int p = 0; p < 2; p++) {
            const int i = bid * 512 + p * 256 + tid;
            const int4   r = er4[i];
            const int4   c = ec4[i];
            const float4 v = ev4[i];
            int pos;
            pos = atomicAdd(&g_cur[r.x], 1); g_epair[pos] = make_int2(c.x, __float_as_int(v.x));
            pos = atomicAdd(&g_cur[r.y], 1); g_epair[pos] = make_int2(c.y, __float_as_int(v.y));
            pos = atomicAdd(&g_cur[r.z], 1); g_epair[pos] = make_int2(c.z, __float_as_int(v.z));
            pos = atomicAdd(&g_cur[r.w], 1); g_epair[pos] = make_int2(c.w, __float_as_int(v.w));
        }
    }
    gbar();

    // ======================= P6: fused SpMM + bias + ReLU ===================
    {
        const int qi  = tid & 7;        // feature octet
        const int sub = tid >> 3;       // row within pass (0..31)
        const float4 b0 = *(const float4*)(bias + qi * 8);
        const float4 b1 = *(const float4*)(bias + qi * 8 + 4);

#pragma unroll
        for (int p = 0; p < 4; p++) {
            const int r = bid * 128 + p * 32 + sub;
            const int s = __ldcg(&g_rs[r]);
            const int e = __ldcg(&g_rs[r + 1]);

            float acc[8];
#pragma unroll
            for (int j = 0; j < 8; j++) acc[j] = 0.f;

            int i = s;
            for (; i + 2 <= e; i += 2) {
                const int2 p0 = g_epair[i];
                const int2 p1 = g_epair[i + 1];
                const float v0 = __int_as_float(p0.y);
                const float v1 = __int_as_float(p1.y);
                const uint4 h0 = *(const uint4*)(g_support_h + ((size_t)p0.x << 6) + (qi << 3));
                const uint4 h1 = *(const uint4*)(g_support_h + ((size_t)p1.x << 6) + (qi << 3));
                float2 f;
                f = __half22float2(*(const __half2*)&h0.x); acc[0] += v0 * f.x; acc[1] += v0 * f.y;
                f = __half22float2(*(const __half2*)&h0.y); acc[2] += v0 * f.x; acc[3] += v0 * f.y;
                f = __half22float2(*(const __half2*)&h0.z); acc[4] += v0 * f.x; acc[5] += v0 * f.y;
                f = __half22float2(*(const __half2*)&h0.w); acc[6] += v0 * f.x; acc[7] += v0 * f.y;
                f = __half22float2(*(const __half2*)&h1.x); acc[0] += v1 * f.x; acc[1] += v1 * f.y;
                f = __half22float2(*(const __half2*)&h1.y); acc[2] += v1 * f.x; acc[3] += v1 * f.y;
                f = __half22float2(*(const __half2*)&h1.z); acc[4] += v1 * f.x; acc[5] += v1 * f.y;
                f = __half22float2(*(const __half2*)&h1.w); acc[6] += v1 * f.x; acc[7] += v1 * f.y;
            }
            if (i < e) {
                const int2 p0 = g_epair[i];
                const float v0 = __int_as_float(p0.y);
                const uint4 h0 = *(const uint4*)(g_support_h + ((size_t)p0.x << 6) + (qi << 3));
                float2 f;
                f = __half22float2(*(const __half2*)&h0.x); acc[0] += v0 * f.x; acc[1] += v0 * f.y;
                f = __half22float2(*(const __half2*)&h0.y); acc[2] += v0 * f.x; acc[3] += v0 * f.y;
                f = __half22float2(*(const __half2*)&h0.z); acc[4] += v0 * f.x; acc[5] += v0 * f.y;
                f = __half22float2(*(const __half2*)&h0.w); acc[6] += v0 * f.x; acc[7] += v0 * f.y;
            }

            float4 o0, o1;
            o0.x = fmaxf(acc[0] + b0.x, 0.f); o0.y = fmaxf(acc[1] + b0.y, 0.f);
            o0.z = fmaxf(acc[2] + b0.z, 0.f); o0.w = fmaxf(acc[3] + b0.w, 0.f);
            o1.x = fmaxf(acc[4] + b1.x, 0.f); o1.y = fmaxf(acc[5] + b1.y, 0.f);
            o1.z = fmaxf(acc[6] + b1.z, 0.f); o1.w = fmaxf(acc[7] + b1.w, 0.f);
            float* po = out + (size_t)r * FEAT + qi * 8;
            *(float4*)po       = o0;
            *(float4*)(po + 4) = o1;
        }
    }
}

// ---------------------------------------------------------------------------
extern "C" void kernel_launch(void* const* d_in, const int* in_sizes, int n_in,
                              void* d_out, int out_size) {
    const float* X    = (const float*)d_in[0];
    const int*   erow = (const int*)  d_in[1];
    const int*   ecol = (const int*)  d_in[2];
    const float* eval = (const float*)d_in[3];
    const float* W    = (const float*)d_in[4];
    const float* bias = (const float*)d_in[5];
    float* out = (float*)d_out;

    gcn_mono<<<NB, NT>>>(X, erow, ecol, eval, W, bias, out);
}

// round 6
// speedup vs baseline: 1.6505x; 1.6505x over previous
#include <cuda_runtime.h>
#include <cuda_fp16.h>
#include <cstdint>

#define N_NODES 65536
#define N_EDGES 1048576
#define FEAT    64

// ------------------------- device scratch (no allocs) -----------------------
__device__ __align__(16) __half g_support_h[(size_t)N_NODES * FEAT]; // 8 MB
__device__ __align__(16) int   g_cnt[N_NODES];   // zero-init; self-cleaned per run
__device__ __align__(16) int   g_rs[N_NODES + 4];
__device__ __align__(16) int   g_cur[N_NODES];
__device__ __align__(16) int   g_bsum[64];
__device__ __align__(16) int2  g_epair[N_EDGES];
__device__ unsigned g_barcnt;
__device__ unsigned g_bargen;

// ---- packed f32x2 helpers ---------------------------------------------------
__device__ __forceinline__ unsigned long long pk2(float x, float y) {
    unsigned long long r;
    asm("mov.b64 %0, {%1, %2};" : "=l"(r) : "f"(x), "f"(y));
    return r;
}
__device__ __forceinline__ void fma2(unsigned long long& d,
                                     unsigned long long a, unsigned long long b) {
    asm("fma.rn.f32x2 %0, %1, %2, %0;" : "+l"(d) : "l"(a), "l"(b));
}
__device__ __forceinline__ float2 up2(unsigned long long v) {
    float2 f;
    asm("mov.b64 {%0, %1}, %2;" : "=f"(f.x), "=f"(f.y) : "l"(v));
    return f;
}

// ---------------------------------------------------------------------------
// Kernel 1: GEMM tile (64 rows) + edge-row histogram chunk (1024 edges).
// Hist atomics overlap the FMA chains; independent outputs, no ordering needed.
// ---------------------------------------------------------------------------
__global__ __launch_bounds__(256) void gemm_hist(const float* __restrict__ X,
                                                 const float* __restrict__ W,
                                                 const int4*  __restrict__ erow4) {
    __shared__ float4 Ws[64][16];
    __shared__ float4 Xs[64][16];

    const int tid  = threadIdx.x;
    const int base = blockIdx.x * 64;

    const float4* X4 = (const float4*)(X + (size_t)base * FEAT);
    const float4* W4 = (const float4*)W;
    float4* XsF = (float4*)Xs;
    float4* WsF = (float4*)Ws;
#pragma unroll
    for (int i = 0; i < 4; i++) {
        const int idx = tid + i * 256;
        XsF[idx] = X4[idx];
        WsF[idx] = W4[idx];
    }

    // histogram chunk: issue atomics early so they drain under the GEMM
    const int4 r = erow4[blockIdx.x * 256 + tid];
    atomicAdd(&g_cnt[r.x], 1);
    atomicAdd(&g_cnt[r.y], 1);
    atomicAdd(&g_cnt[r.z], 1);
    atomicAdd(&g_cnt[r.w], 1);

    __syncthreads();

    const int rt = tid >> 4;
    const int ct = tid & 15;

    unsigned long long acc[4][2];
#pragma unroll
    for (int i = 0; i < 4; i++) { acc[i][0] = pk2(0.f, 0.f); acc[i][1] = pk2(0.f, 0.f); }

#pragma unroll
    for (int kk = 0; kk < 16; kk++) {
        const float4 w0 = Ws[kk * 4 + 0][ct];
        const float4 w1 = Ws[kk * 4 + 1][ct];
        const float4 w2 = Ws[kk * 4 + 2][ct];
        const float4 w3 = Ws[kk * 4 + 3][ct];
        const unsigned long long wp00 = pk2(w0.x, w0.y), wp01 = pk2(w0.z, w0.w);
        const unsigned long long wp10 = pk2(w1.x, w1.y), wp11 = pk2(w1.z, w1.w);
        const unsigned long long wp20 = pk2(w2.x, w2.y), wp21 = pk2(w2.z, w2.w);
        const unsigned long long wp30 = pk2(w3.x, w3.y), wp31 = pk2(w3.z, w3.w);
#pragma unroll
        for (int i = 0; i < 4; i++) {
            const float4 x = Xs[rt + 16 * i][kk];
            unsigned long long xx;
            xx = pk2(x.x, x.x); fma2(acc[i][0], xx, wp00); fma2(acc[i][1], xx, wp01);
            xx = pk2(x.y, x.y); fma2(acc[i][0], xx, wp10); fma2(acc[i][1], xx, wp11);
            xx = pk2(x.z, x.z); fma2(acc[i][0], xx, wp20); fma2(acc[i][1], xx, wp21);
            xx = pk2(x.w, x.w); fma2(acc[i][0], xx, wp30); fma2(acc[i][1], xx, wp31);
        }
    }

#pragma unroll
    for (int i = 0; i < 4; i++) {
        const int row = base + rt + 16 * i;
        const float2 a = up2(acc[i][0]);
        const float2 b = up2(acc[i][1]);
        const __half2 ha = __floats2half2_rn(a.x, a.y);
        const __half2 hb = __floats2half2_rn(b.x, b.y);
        uint2 st;
        st.x = *(const unsigned*)&ha;
        st.y = *(const unsigned*)&hb;
        *(uint2*)(g_support_h + (size_t)row * FEAT + ct * 4) = st;
    }
}

// ---------------------------------------------------------------------------
// Kernel 2: full CSR scan in ONE kernel. Grid = 64 blocks (always co-resident)
// with an internal grid barrier. Also self-cleans g_cnt and seeds g_cur.
// ---------------------------------------------------------------------------
__device__ __forceinline__ void gbar64() {
    __syncthreads();
    if (threadIdx.x == 0) {
        __threadfence();
        const unsigned gen = *(volatile unsigned*)&g_bargen;
        if (atomicAdd(&g_barcnt, 1u) == 63u) {
            g_barcnt = 0;
            __threadfence();
            *(volatile unsigned*)&g_bargen = gen + 1u;
        } else {
            while (*(volatile unsigned*)&g_bargen == gen) { __nanosleep(32); }
        }
    }
    __syncthreads();
}

__global__ __launch_bounds__(256) void scan_fused() {
    __shared__ int wsum[8];
    const int tid = threadIdx.x;
    const int bid = blockIdx.x;
    const int i = bid * 256 + tid;

    // ---- P1: per-block scan of 4-wide counts ----
    const int4 c = ((const int4*)g_cnt)[i];
    const int s = c.x + c.y + c.z + c.w;

    const int lane = tid & 31, wid = tid >> 5;
    int x = s;
#pragma unroll
    for (int d = 1; d < 32; d <<= 1) {
        const int y = __shfl_up_sync(0xFFFFFFFFu, x, d);
        if (lane >= d) x += y;
    }
    if (lane == 31) wsum[wid] = x;
    __syncthreads();
    if (wid == 0) {
        int w = (lane < 8) ? wsum[lane] : 0;
#pragma unroll
        for (int d = 1; d < 8; d <<= 1) {
            const int y = __shfl_up_sync(0xFFFFFFFFu, w, d);
            if (lane >= d) w += y;
        }
        if (lane < 8) wsum[lane] = w;
    }
    __syncthreads();
    const int incl = x + (wid > 0 ? wsum[wid - 1] : 0);
    const int ex = incl - s;
    if (tid == 255) g_bsum[bid] = incl;
    gbar64();

    // ---- P2: block 0 warp 0 scans the 64 block sums ----
    if (bid == 0 && tid < 32) {
        const int a = __ldcg(&g_bsum[tid]);
        const int b = __ldcg(&g_bsum[tid + 32]);
        int ia = a, ib = b;
#pragma unroll
        for (int d = 1; d < 32; d <<= 1) {
            const int ya = __shfl_up_sync(0xFFFFFFFFu, ia, d);
            const int yb = __shfl_up_sync(0xFFFFFFFFu, ib, d);
            if (tid >= d) { ia += ya; ib += yb; }
        }
        const int lowtot = __shfl_sync(0xFFFFFFFFu, ia, 31);
        g_bsum[tid]      = ia - a;
        g_bsum[tid + 32] = lowtot + ib - b;
    }
    gbar64();

    // ---- P3: write row starts + cursors, clean counts ----
    const int off = __ldcg(&g_bsum[bid]) + ex;
    const int4 rs = make_int4(off, off + c.x, off + c.x + c.y, off + c.x + c.y + c.z);
    ((int4*)g_rs)[i]  = rs;
    ((int4*)g_cur)[i] = rs;
    ((int4*)g_cnt)[i] = make_int4(0, 0, 0, 0);
    if (i == 0) g_rs[N_NODES] = N_EDGES;
}

// ---------------------------------------------------------------------------
// Kernel 3: reorder edges into CSR (col, val) pairs
// ---------------------------------------------------------------------------
__global__ __launch_bounds__(256) void reorder(const int4*   __restrict__ erow4,
                                               const int4*   __restrict__ ecol4,
                                               const float4* __restrict__ eval4) {
    const unsigned i = blockIdx.x * 256u + threadIdx.x;
    const int4   r = erow4[i];
    const int4   c = ecol4[i];
    const float4 v = eval4[i];
    int p;
    p = atomicAdd(&g_cur[r.x], 1); g_epair[p] = make_int2(c.x, __float_as_int(v.x));
    p = atomicAdd(&g_cur[r.y], 1); g_epair[p] = make_int2(c.y, __float_as_int(v.y));
    p = atomicAdd(&g_cur[r.z], 1); g_epair[p] = make_int2(c.z, __float_as_int(v.z));
    p = atomicAdd(&g_cur[r.w], 1); g_epair[p] = make_int2(c.w, __float_as_int(v.w));
}

// ---------------------------------------------------------------------------
// Kernel 4: SpMM + bias + ReLU (atomic-free), fp16 gather, fp32 accumulate
// 8 threads per row; 32 rows per block.
// ---------------------------------------------------------------------------
__global__ __launch_bounds__(256) void spmm_fused(float* __restrict__ out,
                                                  const float* __restrict__ bias) {
    const int r  = blockIdx.x * 32 + (threadIdx.x >> 3);
    const int qi = threadIdx.x & 7;

    const int s = g_rs[r];
    const int e = g_rs[r + 1];

    float acc[8];
#pragma unroll
    for (int j = 0; j < 8; j++) acc[j] = 0.f;

    int i = s;
    for (; i + 2 <= e; i += 2) {
        const int2 p0 = g_epair[i];
        const int2 p1 = g_epair[i + 1];
        const float v0 = __int_as_float(p0.y);
        const float v1 = __int_as_float(p1.y);
        const uint4 h0 = *(const uint4*)(g_support_h + ((size_t)p0.x << 6) + (qi << 3));
        const uint4 h1 = *(const uint4*)(g_support_h + ((size_t)p1.x << 6) + (qi << 3));
        float2 f;
        f = __half22float2(*(const __half2*)&h0.x); acc[0] += v0 * f.x; acc[1] += v0 * f.y;
        f = __half22float2(*(const __half2*)&h0.y); acc[2] += v0 * f.x; acc[3] += v0 * f.y;
        f = __half22float2(*(const __half2*)&h0.z); acc[4] += v0 * f.x; acc[5] += v0 * f.y;
        f = __half22float2(*(const __half2*)&h0.w); acc[6] += v0 * f.x; acc[7] += v0 * f.y;
        f = __half22float2(*(const __half2*)&h1.x); acc[0] += v1 * f.x; acc[1] += v1 * f.y;
        f = __half22float2(*(const __half2*)&h1.y); acc[2] += v1 * f.x; acc[3] += v1 * f.y;
        f = __half22float2(*(const __half2*)&h1.z); acc[4] += v1 * f.x; acc[5] += v1 * f.y;
        f = __half22float2(*(const __half2*)&h1.w); acc[6] += v1 * f.x; acc[7] += v1 * f.y;
    }
    if (i < e) {
        const int2 p0 = g_epair[i];
        const float v0 = __int_as_float(p0.y);
        const uint4 h0 = *(const uint4*)(g_support_h + ((size_t)p0.x << 6) + (qi << 3));
        float2 f;
        f = __half22float2(*(const __half2*)&h0.x); acc[0] += v0 * f.x; acc[1] += v0 * f.y;
        f = __half22float2(*(const __half2*)&h0.y); acc[2] += v0 * f.x; acc[3] += v0 * f.y;
        f = __half22float2(*(const __half2*)&h0.z); acc[4] += v0 * f.x; acc[5] += v0 * f.y;
        f = __half22float2(*(const __half2*)&h0.w); acc[6] += v0 * f.x; acc[7] += v0 * f.y;
    }

    const float4 b0 = *(const float4*)(bias + qi * 8);
    const float4 b1 = *(const float4*)(bias + qi * 8 + 4);
    float4 o0, o1;
    o0.x = fmaxf(acc[0] + b0.x, 0.f); o0.y = fmaxf(acc[1] + b0.y, 0.f);
    o0.z = fmaxf(acc[2] + b0.z, 0.f); o0.w = fmaxf(acc[3] + b0.w, 0.f);
    o1.x = fmaxf(acc[4] + b1.x, 0.f); o1.y = fmaxf(acc[5] + b1.y, 0.f);
    o1.z = fmaxf(acc[6] + b1.z, 0.f); o1.w = fmaxf(acc[7] + b1.w, 0.f);
    float* po = out + (size_t)r * FEAT + qi * 8;
    *(float4*)po       = o0;
    *(float4*)(po + 4) = o1;
}

// ---------------------------------------------------------------------------
extern "C" void kernel_launch(void* const* d_in, const int* in_sizes, int n_in,
                              void* d_out, int out_size) {
    const float* X    = (const float*)d_in[0];
    const int*   erow = (const int*)  d_in[1];
    const int*   ecol = (const int*)  d_in[2];
    const float* eval = (const float*)d_in[3];
    const float* W    = (const float*)d_in[4];
    const float* bias = (const float*)d_in[5];
    float* out = (float*)d_out;

    gemm_hist<<<N_NODES / 64, 256>>>(X, W, (const int4*)erow);   // GEMM + histogram
    scan_fused<<<64, 256>>>();                                   // full CSR scan
    reorder<<<N_EDGES / 1024, 256>>>((const int4*)erow, (const int4*)ecol,
                                     (const float4*)eval);
    spmm_fused<<<N_NODES / 32, 256>>>(out, bias);                // SpMM + bias + ReLU
}